// round 1
// baseline (speedup 1.0000x reference)
#include <cuda_runtime.h>

#define NN   20000
#define EE   320000
#define FIN  512
#define HID  64
#define LL   9
#define NTPL 10
#define NTN  8
#define NCLS 6

// scratch (no cudaMalloc allowed)
__device__ float g_bufA[NN * HID];
__device__ float g_bufB[NN * HID];
__device__ float g_bufC[NN * HID];
__device__ float g_dinv[NN];

// ---------------- degree / dinv ----------------
__global__ void k_deg_init() {
    int i = blockIdx.x * blockDim.x + threadIdx.x;
    if (i < NN) g_dinv[i] = 1.0f;   // self loop
}
__global__ void k_deg_edge(const int* __restrict__ dst) {
    int e = blockIdx.x * blockDim.x + threadIdx.x;
    if (e < EE) atomicAdd(&g_dinv[dst[e]], 1.0f);
}
__global__ void k_deg_fin() {
    int i = blockIdx.x * blockDim.x + threadIdx.x;
    if (i < NN) g_dinv[i] = rsqrtf(g_dinv[i]);
}

// ---------------- GEMM: out = (relu?)A[M,K] @ W[K,64]; epilogue writes xw and self-loop init ----------------
template <bool RELU>
__global__ __launch_bounds__(256) void k_gemm(
    const float* __restrict__ A, const float* __restrict__ W,
    const float* __restrict__ bias, float* __restrict__ oXW,
    float* __restrict__ oH, int M, int K, int lda)
{
    __shared__ float As[64][68];
    __shared__ float Bs[64][64];
    const int t  = threadIdx.x;
    const int tx = t & 15, ty = t >> 4;
    const int row0 = blockIdx.x * 64;

    float acc[4][4];
#pragma unroll
    for (int i = 0; i < 4; i++)
#pragma unroll
        for (int c = 0; c < 4; c++) acc[i][c] = 0.f;

    for (int kt = 0; kt < K; kt += 64) {
#pragma unroll
        for (int p = 0; p < 4; p++) {
            int v = t + 256 * p;
            int r = v >> 4, c4 = v & 15;
            int gr = row0 + r;
            float4 val = make_float4(0.f, 0.f, 0.f, 0.f);
            if (gr < M) val = *(const float4*)(A + (size_t)gr * lda + kt + c4 * 4);
            if (RELU) {
                val.x = fmaxf(val.x, 0.f); val.y = fmaxf(val.y, 0.f);
                val.z = fmaxf(val.z, 0.f); val.w = fmaxf(val.w, 0.f);
            }
            *(float4*)&As[r][c4 * 4] = val;
        }
#pragma unroll
        for (int p = 0; p < 4; p++) {
            int v = t + 256 * p;
            int r = v >> 4, c4 = v & 15;
            *(float4*)&Bs[r][c4 * 4] = *(const float4*)(W + (size_t)(kt + r) * HID + c4 * 4);
        }
        __syncthreads();
#pragma unroll
        for (int k = 0; k < 64; k += 4) {
            float4 a4[4], b4[4];
#pragma unroll
            for (int i = 0; i < 4; i++) a4[i] = *(const float4*)&As[ty * 4 + i][k];
#pragma unroll
            for (int kk = 0; kk < 4; kk++) b4[kk] = *(const float4*)&Bs[k + kk][tx * 4];
#pragma unroll
            for (int i = 0; i < 4; i++) {
                acc[i][0] += a4[i].x*b4[0].x + a4[i].y*b4[1].x + a4[i].z*b4[2].x + a4[i].w*b4[3].x;
                acc[i][1] += a4[i].x*b4[0].y + a4[i].y*b4[1].y + a4[i].z*b4[2].y + a4[i].w*b4[3].y;
                acc[i][2] += a4[i].x*b4[0].z + a4[i].y*b4[1].z + a4[i].z*b4[2].z + a4[i].w*b4[3].z;
                acc[i][3] += a4[i].x*b4[0].w + a4[i].y*b4[1].w + a4[i].z*b4[2].w + a4[i].w*b4[3].w;
            }
        }
        __syncthreads();
    }
#pragma unroll
    for (int i = 0; i < 4; i++) {
        int gr = row0 + ty * 4 + i;
        if (gr < M) {
            float dv = g_dinv[gr];
            float dv2 = dv * dv;
#pragma unroll
            for (int c = 0; c < 4; c++) {
                int col = tx * 4 + c;
                float xw = acc[i][c];
                oXW[(size_t)gr * HID + col] = xw;
                oH[(size_t)gr * HID + col] = xw * dv2 + bias[col];   // self-loop + bias
            }
        }
    }
}

// ---------------- edge scatter: h[dst] += xw[src] * dinv[src]*dinv[dst] ----------------
__global__ __launch_bounds__(256) void k_scatter(
    const float* __restrict__ xw, float* __restrict__ h,
    const int* __restrict__ src, const int* __restrict__ dst)
{
    unsigned idx = blockIdx.x * 256u + threadIdx.x;
    int e = idx >> 6;
    int f = idx & 63;
    if (e < EE) {
        int s = src[e], d = dst[e];
        float c = g_dinv[s] * g_dinv[d];
        atomicAdd(&h[(size_t)d * HID + f], xw[(size_t)s * HID + f] * c);
    }
}

// ---------------- distance-to-template (FGW) + final linear ----------------
// Block = 160 threads = 2 nodes * 80 (10 templates * 8 cols). Thread (tpl,j) owns
// column j of the 9x8 coupling in registers; group-of-8 shuffles do K@v and A@C2.
__global__ __launch_bounds__(160) void k_dist(
    const float* __restrict__ h,        // [NN,64]
    const int*   __restrict__ nbr_idx,  // [NN,8]
    const float* __restrict__ nbr_mask, // [NN,9]
    const float* __restrict__ C_local,  // [NN,9,9]
    const float* __restrict__ tfeat,    // [10,8,64]
    const float* __restrict__ tadj,     // [10,8,8] symmetric
    const float* __restrict__ Wlin,     // [74,6]
    const float* __restrict__ blin,     // [6]
    float* __restrict__ out)            // [NN,6]
{
    __shared__ float xl[2][LL][HID];
    __shared__ float C1s[2][LL][LL];
    __shared__ float f1h1s[2][LL];
    __shared__ float h1ss[2][LL];
    __shared__ float sxn[2][LL];
    __shared__ float ys[2][NTPL];
    __shared__ int   idxs[2][LL];

    const int tid = threadIdx.x;
    const int ns  = tid / 80;
    const int r   = tid % 80;
    const int node = blockIdx.x * 2 + ns;
    const int tpl = r >> 3;
    const int j   = r & 7;
    const unsigned FULL = 0xffffffffu;

    if (r < LL)
        idxs[ns][r] = (r == 0) ? node : nbr_idx[node * (LL - 1) + (r - 1)];
    __syncthreads();

    for (int q = r; q < LL * HID; q += 80) {
        int i = q >> 6, f = q & 63;
        xl[ns][i][f] = h[(size_t)idxs[ns][i] * HID + f];
    }
    if (r < LL * LL)
        C1s[ns][r / LL][r % LL] = C_local[(size_t)node * LL * LL + r];
    if (r < LL) {
        float s = 0.f;
#pragma unroll
        for (int k = 0; k < LL; k++) s += nbr_mask[node * LL + k];
        h1ss[ns][r] = nbr_mask[node * LL + r] / s;
    }
    __syncthreads();
    if (r < LL) {
        float s = 0.f;
#pragma unroll
        for (int k = 0; k < LL; k++) s += C1s[ns][r][k] * h1ss[ns][k];  // C1 is 0/1 so C1^2==C1
        f1h1s[ns][r] = s;
        float q2 = 0.f;
#pragma unroll
        for (int f = 0; f < HID; f++) { float xv = xl[ns][r][f]; q2 += xv * xv; }
        sxn[ns][r] = q2;
    }
    __syncthreads();

    // cost column M[:,j] for this template
    float Mcol[LL];
    {
        float acc[LL];
#pragma unroll
        for (int i = 0; i < LL; i++) acc[i] = 0.f;
        float tn = 0.f;
        const float4* tf4 = (const float4*)(tfeat + (size_t)(tpl * NTN + j) * HID);
#pragma unroll 4
        for (int c = 0; c < 16; c++) {
            float4 t4 = __ldg(&tf4[c]);
            tn += t4.x*t4.x + t4.y*t4.y + t4.z*t4.z + t4.w*t4.w;
#pragma unroll
            for (int i = 0; i < LL; i++) {
                float4 x4 = *(const float4*)&xl[ns][i][c * 4];
                acc[i] += x4.x*t4.x + x4.y*t4.y + x4.z*t4.z + x4.w*t4.w;
            }
        }
#pragma unroll
        for (int i = 0; i < LL; i++)
            Mcol[i] = sxn[ns][i] + tn - 2.f * acc[i];
    }

    float C2col[NTN];
#pragma unroll
    for (int m = 0; m < NTN; m++)
        C2col[m] = tadj[(size_t)(tpl * NTN + j) * NTN + m];   // symmetric: row j == col j
    float f2h2 = 0.f;
#pragma unroll
    for (int m = 0; m < NTN; m++) f2h2 += C2col[m] * C2col[m];
    f2h2 *= 0.125f;

    float h1r[LL], cc[LL];
#pragma unroll
    for (int i = 0; i < LL; i++) {
        h1r[i] = h1ss[ns][i];
        cc[i]  = f1h1s[ns][i] + f2h2;
    }

    float Tcol[LL];
#pragma unroll
    for (int i = 0; i < LL; i++) Tcol[i] = h1r[i] * 0.125f;

    float Kcol[LL];
    for (int outer = 0; outer < 3; outer++) {
        float Acol[LL], Bcol[LL];
#pragma unroll
        for (int i = 0; i < LL; i++) {
            float s = 0.f;
#pragma unroll
            for (int k = 0; k < LL; k++) s += C1s[ns][i][k] * Tcol[k];
            Acol[i] = s; Bcol[i] = 0.f;
        }
#pragma unroll
        for (int m = 0; m < NTN; m++) {
            float c2 = C2col[m];
#pragma unroll
            for (int i = 0; i < LL; i++)
                Bcol[i] += __shfl_sync(FULL, Acol[i], m, 8) * c2;
        }
#pragma unroll
        for (int i = 0; i < LL; i++) {
            float tens = cc[i] - 2.f * Bcol[i];
            float G = 0.5f * (Mcol[i] + tens);          // alpha = 0.5
            Kcol[i] = __expf(-10.f * G);                 // 1/eps = 10
        }
        float v = 1.f;
        float u[LL];
        for (int it = 0; it < 5; it++) {
#pragma unroll
            for (int i = 0; i < LL; i++) {
                float tkv = Kcol[i] * v;
                tkv += __shfl_xor_sync(FULL, tkv, 1, 8);
                tkv += __shfl_xor_sync(FULL, tkv, 2, 8);
                tkv += __shfl_xor_sync(FULL, tkv, 4, 8);
                u[i] = __fdividef(h1r[i], tkv + 1e-16f);
            }
            float den = 0.f;
#pragma unroll
            for (int i = 0; i < LL; i++) den += Kcol[i] * u[i];
            v = __fdividef(0.125f, den + 1e-16f);
        }
#pragma unroll
        for (int i = 0; i < LL; i++) Tcol[i] = u[i] * Kcol[i] * v;
    }

    // final tens with converged T, then fused FGW objective
    {
        float Acol[LL], Bcol[LL];
#pragma unroll
        for (int i = 0; i < LL; i++) {
            float s = 0.f;
#pragma unroll
            for (int k = 0; k < LL; k++) s += C1s[ns][i][k] * Tcol[k];
            Acol[i] = s; Bcol[i] = 0.f;
        }
#pragma unroll
        for (int m = 0; m < NTN; m++) {
            float c2 = C2col[m];
#pragma unroll
            for (int i = 0; i < LL; i++)
                Bcol[i] += __shfl_sync(FULL, Acol[i], m, 8) * c2;
        }
        float local = 0.f;
#pragma unroll
        for (int i = 0; i < LL; i++) {
            float tens = cc[i] - 2.f * Bcol[i];
            local += Tcol[i] * 0.5f * (Mcol[i] + tens);
        }
        local += __shfl_xor_sync(FULL, local, 1, 8);
        local += __shfl_xor_sync(FULL, local, 2, 8);
        local += __shfl_xor_sync(FULL, local, 4, 8);
        if (j == 0) ys[ns][tpl] = local;
    }
    __syncthreads();

    // out = relu(concat(h, y) @ Wlin + blin)   (h row == xl[ns][0])
    if (r < NCLS) {
        float acc = blin[r];
#pragma unroll 8
        for (int k = 0; k < HID; k++) acc += xl[ns][0][k] * Wlin[k * NCLS + r];
#pragma unroll
        for (int tt = 0; tt < NTPL; tt++) acc += ys[ns][tt] * Wlin[(HID + tt) * NCLS + r];
        out[node * NCLS + r] = fmaxf(acc, 0.f);
    }
}

// ---------------- launch ----------------
extern "C" void kernel_launch(void* const* d_in, const int* in_sizes, int n_in,
                              void* d_out, int out_size)
{
    const float* x     = (const float*)d_in[0];
    const int*   ei    = (const int*)  d_in[1];
    const int*   nbr   = (const int*)  d_in[2];
    const float* mask  = (const float*)d_in[3];
    const float* Cl    = (const float*)d_in[4];
    const float* W1    = (const float*)d_in[5];
    const float* b1    = (const float*)d_in[6];
    const float* W2    = (const float*)d_in[7];
    const float* b2    = (const float*)d_in[8];
    const float* tadj  = (const float*)d_in[9];
    const float* tfeat = (const float*)d_in[10];
    const float* Wlin  = (const float*)d_in[11];
    const float* blin  = (const float*)d_in[12];
    float* out = (float*)d_out;

    const int* src = ei;
    const int* dst = ei + EE;

    void *pA, *pB, *pC;
    cudaGetSymbolAddress(&pA, g_bufA);
    cudaGetSymbolAddress(&pB, g_bufB);
    cudaGetSymbolAddress(&pC, g_bufC);
    float* bufA = (float*)pA;
    float* bufB = (float*)pB;
    float* bufC = (float*)pC;

    k_deg_init<<<(NN + 255) / 256, 256>>>();
    k_deg_edge<<<(EE + 255) / 256, 256>>>(dst);
    k_deg_fin<<<(NN + 255) / 256, 256>>>();

    // layer 1: xw1 = x@W1 ; h1 = self + bias ; scatter edges
    k_gemm<false><<<(NN + 63) / 64, 256>>>(x, W1, b1, bufA, bufB, NN, FIN, FIN);
    k_scatter<<<(EE * HID) / 256, 256>>>(bufA, bufB, src, dst);

    // layer 2: xw2 = relu(h1)@W2 ; h2 = self + bias ; scatter edges
    k_gemm<true><<<(NN + 63) / 64, 256>>>(bufB, W2, b2, bufA, bufC, NN, HID, HID);
    k_scatter<<<(EE * HID) / 256, 256>>>(bufA, bufC, src, dst);

    // FGW distances + final linear head
    k_dist<<<NN / 2, 160>>>(bufC, nbr, mask, Cl, tfeat, tadj, Wlin, blin, out);
}

// round 3
// speedup vs baseline: 1.6372x; 1.6372x over previous
#include <cuda_runtime.h>

#define NN   20000
#define EE   320000
#define FIN  512
#define HID  64
#define LL   9
#define NTPL 10
#define NTN  8
#define NCLS 6
#define NB   16      // nodes per k_dist block

// -------- scratch (no cudaMalloc allowed) --------
__device__ float g_bufA[NN * HID];
__device__ float g_bufB[NN * HID];
__device__ float g_bufC[NN * HID];
__device__ float g_dinv[NN];
__device__ int   g_cnt[NN];
__device__ int   g_off[NN + 1];
__device__ int   g_cur[NN];
__device__ int   g_csrc[EE];
__device__ float g_coef[EE];
__device__ float g_R[NN * 80];     // ||h||^2 - 2 * h @ tfeat^T
__device__ float g_tn[80];         // ||tfeat row||^2

// ---------------- CSR build ----------------
__global__ void k_zero() {
    int i = blockIdx.x * blockDim.x + threadIdx.x;
    if (i < NN) g_cnt[i] = 0;
}
__global__ void k_count(const int* __restrict__ dst) {
    int e = blockIdx.x * blockDim.x + threadIdx.x;
    if (e < EE) atomicAdd(&g_cnt[dst[e]], 1);
}
__global__ void k_dinv() {
    int i = blockIdx.x * blockDim.x + threadIdx.x;
    if (i < NN) g_dinv[i] = rsqrtf((float)g_cnt[i] + 1.0f);
}
__global__ __launch_bounds__(1024) void k_scan() {
    const int t = threadIdx.x;
    const int base = t * 20;
    int loc[20]; int s = 0;
#pragma unroll
    for (int j = 0; j < 20; j++) {
        int idx = base + j;
        int v = (idx < NN) ? g_cnt[idx] : 0;
        loc[j] = s; s += v;
    }
    const unsigned FULL = 0xffffffffu;
    int lane = t & 31, w = t >> 5;
    int x = s;
#pragma unroll
    for (int d = 1; d < 32; d <<= 1) { int y = __shfl_up_sync(FULL, x, d); if (lane >= d) x += y; }
    __shared__ int ws[32];
    if (lane == 31) ws[w] = x;
    __syncthreads();
    if (w == 0) {
        int y = ws[lane];
#pragma unroll
        for (int d = 1; d < 32; d <<= 1) { int z = __shfl_up_sync(FULL, y, d); if (lane >= d) y += z; }
        ws[lane] = y;
    }
    __syncthreads();
    int excl = x - s + (w > 0 ? ws[w - 1] : 0);
#pragma unroll
    for (int j = 0; j < 20; j++) {
        int idx = base + j;
        if (idx < NN) { int o = excl + loc[j]; g_off[idx] = o; g_cur[idx] = o; }
    }
    if (t == 1023) g_off[NN] = ws[31];
}
__global__ void k_fill(const int* __restrict__ src, const int* __restrict__ dst) {
    int e = blockIdx.x * blockDim.x + threadIdx.x;
    if (e < EE) {
        int s = src[e], d = dst[e];
        int pos = atomicAdd(&g_cur[d], 1);
        g_csrc[pos] = s;
        g_coef[pos] = g_dinv[s] * g_dinv[d];
    }
}

// ---------------- GEMM: out = (relu?)A[M,K] @ W[K,64]; epilogue: xw + self-loop init ----------------
template <bool RELU>
__global__ __launch_bounds__(128) void k_gemm(
    const float* __restrict__ A, const float* __restrict__ W,
    const float* __restrict__ bias, float* __restrict__ oXW,
    float* __restrict__ oH, int M, int K, int lda)
{
    __shared__ float As[64][68];
    __shared__ float Bs[64][64];
    const int t  = threadIdx.x;
    const int tx = t & 15, ty = t >> 4;      // ty 0..7 -> 8 rows each; tx -> 4 cols
    const int row0 = blockIdx.x * 64;

    float acc[8][4];
#pragma unroll
    for (int i = 0; i < 8; i++)
#pragma unroll
        for (int c = 0; c < 4; c++) acc[i][c] = 0.f;

    for (int kt = 0; kt < K; kt += 64) {
#pragma unroll
        for (int p = 0; p < 8; p++) {
            int v = t + 128 * p;
            int r = v >> 4, c4 = v & 15;
            int gr = row0 + r;
            float4 val = make_float4(0.f, 0.f, 0.f, 0.f);
            if (gr < M) val = *(const float4*)(A + (size_t)gr * lda + kt + c4 * 4);
            if (RELU) {
                val.x = fmaxf(val.x, 0.f); val.y = fmaxf(val.y, 0.f);
                val.z = fmaxf(val.z, 0.f); val.w = fmaxf(val.w, 0.f);
            }
            *(float4*)&As[r][c4 * 4] = val;
        }
#pragma unroll
        for (int p = 0; p < 8; p++) {
            int v = t + 128 * p;
            int r = v >> 4, c4 = v & 15;
            *(float4*)&Bs[r][c4 * 4] = *(const float4*)(W + (size_t)(kt + r) * HID + c4 * 4);
        }
        __syncthreads();
#pragma unroll
        for (int k = 0; k < 64; k += 4) {
            float4 a4[8], b4[4];
#pragma unroll
            for (int i = 0; i < 8; i++) a4[i] = *(const float4*)&As[ty * 8 + i][k];
#pragma unroll
            for (int kk = 0; kk < 4; kk++) b4[kk] = *(const float4*)&Bs[k + kk][tx * 4];
#pragma unroll
            for (int i = 0; i < 8; i++) {
                acc[i][0] += a4[i].x*b4[0].x + a4[i].y*b4[1].x + a4[i].z*b4[2].x + a4[i].w*b4[3].x;
                acc[i][1] += a4[i].x*b4[0].y + a4[i].y*b4[1].y + a4[i].z*b4[2].y + a4[i].w*b4[3].y;
                acc[i][2] += a4[i].x*b4[0].z + a4[i].y*b4[1].z + a4[i].z*b4[2].z + a4[i].w*b4[3].z;
                acc[i][3] += a4[i].x*b4[0].w + a4[i].y*b4[1].w + a4[i].z*b4[2].w + a4[i].w*b4[3].w;
            }
        }
        __syncthreads();
    }
#pragma unroll
    for (int i = 0; i < 8; i++) {
        int gr = row0 + ty * 8 + i;
        if (gr < M) {
            float dv = g_dinv[gr];
            float dv2 = dv * dv;
#pragma unroll
            for (int c = 0; c < 4; c++) {
                int col = tx * 4 + c;
                float xw = acc[i][c];
                oXW[(size_t)gr * HID + col] = xw;
                oH[(size_t)gr * HID + col] = xw * dv2 + bias[col];
            }
        }
    }
}

// ---------------- gather: h[d][f] += sum_in-edges coef * xw[s][f] ----------------
__global__ __launch_bounds__(256) void k_gather(
    const float* __restrict__ xw, float* __restrict__ h)
{
    int d = blockIdx.x * 4 + (threadIdx.x >> 6);
    int f = threadIdx.x & 63;
    if (d >= NN) return;
    int e  = g_off[d];
    int s1 = g_off[d + 1];
    float acc = h[(size_t)d * HID + f];
    for (; e + 1 < s1; e += 2) {
        int   sa = g_csrc[e],     sb = g_csrc[e + 1];
        float ca = g_coef[e],     cb = g_coef[e + 1];
        float va = xw[(size_t)sa * HID + f];
        float vb = xw[(size_t)sb * HID + f];
        acc += va * ca + vb * cb;
    }
    if (e < s1) acc += xw[(size_t)g_csrc[e] * HID + f] * g_coef[e];
    h[(size_t)d * HID + f] = acc;
}

// ---------------- template norms ----------------
__global__ void k_tn(const float* __restrict__ tfeat) {
    int t = threadIdx.x;
    if (t < 80) {
        float s = 0.f;
#pragma unroll
        for (int k = 0; k < HID; k++) { float v = tfeat[t * HID + k]; s += v * v; }
        g_tn[t] = s;
    }
}

// ---------------- R = ||h||^2 - 2 * h @ tfeat^T : [NN, 80] ----------------
__global__ __launch_bounds__(256) void k_pr(
    const float* __restrict__ h, const float* __restrict__ tfeat)
{
    __shared__ float hs[64][68];    // stride 68 floats = 272 B -> float4-aligned rows
    __shared__ float tfs[64][81];   // transposed [k][tm], scalar access only
    const int t = threadIdx.x;
    const int r0 = blockIdx.x * 64;
#pragma unroll
    for (int p = 0; p < 4; p++) {
        int v = t + 256 * p;
        int r = v >> 4, c4 = v & 15;
        int gr = r0 + r;
        float4 val = make_float4(0.f, 0.f, 0.f, 0.f);
        if (gr < NN) val = *(const float4*)(h + (size_t)gr * HID + c4 * 4);
        *(float4*)&hs[r][c4 * 4] = val;
    }
    for (int q = t; q < 80 * 64; q += 256) {
        int tm = q >> 6, k = q & 63;
        tfs[k][tm] = tfeat[q];
    }
    __syncthreads();
    const int ty = t >> 4, tx = t & 15;  // 4 rows, 5 cols
    float acc[4][5];
    float h2[4];
#pragma unroll
    for (int i = 0; i < 4; i++) { h2[i] = 0.f;
#pragma unroll
        for (int c = 0; c < 5; c++) acc[i][c] = 0.f; }
#pragma unroll
    for (int k = 0; k < 64; k++) {
        float a[4], b[5];
#pragma unroll
        for (int i = 0; i < 4; i++) a[i] = hs[ty * 4 + i][k];
#pragma unroll
        for (int c = 0; c < 5; c++) b[c] = tfs[k][tx * 5 + c];
#pragma unroll
        for (int i = 0; i < 4; i++) {
            h2[i] += a[i] * a[i];
#pragma unroll
            for (int c = 0; c < 5; c++) acc[i][c] += a[i] * b[c];
        }
    }
#pragma unroll
    for (int i = 0; i < 4; i++) {
        int gr = r0 + ty * 4 + i;
        if (gr < NN) {
#pragma unroll
            for (int c = 0; c < 5; c++)
                g_R[(size_t)gr * 80 + tx * 5 + c] = h2[i] - 2.f * acc[i][c];
        }
    }
}

// ---------------- FGW distances (scalar per node x template) + linear head ----------------
__global__ __launch_bounds__(160, 2) void k_dist(
    const float* __restrict__ h,
    const int*   __restrict__ nbr_idx,
    const float* __restrict__ nbr_mask,
    const float* __restrict__ C_local,
    const float* __restrict__ tadj,     // [10,8,8]
    const float* __restrict__ Wlin,     // [74,6]
    const float* __restrict__ blin,
    float* __restrict__ out)
{
    extern __shared__ float sm[];
    float* Msh  = sm;                     // [72][160]  S = -5*(M + constC)
    float* C1s  = Msh  + 72 * 160;        // [NB][84]
    float* h1sh = C1s  + NB * 84;         // [NB][9]
    float* f1h1 = h1sh + NB * 9;          // [NB][9]
    float* C2s  = f1h1 + NB * 9;          // [10][64]
    float* ysh  = C2s  + 640;             // [NB][10]
    float* tns  = ysh  + NB * 10;         // [80]
    int*   idxs = (int*)(tns + 80);       // [NB][9]

    const int tid = threadIdx.x;
    const int nl  = tid / 10;
    const int tpl = tid % 10;
    const int node0 = blockIdx.x * NB;

    if (tid < 80) tns[tid] = g_tn[tid];
    for (int q = tid; q < 640; q += 160) C2s[q] = tadj[q];
    for (int q = tid; q < NB * 9; q += 160) {
        int nn = q / 9, i = q % 9;
        idxs[nn * 9 + i] = (i == 0) ? (node0 + nn) : nbr_idx[(node0 + nn) * 8 + i - 1];
    }
    for (int q = tid; q < NB * 81; q += 160) {
        int nn = q / 81, r = q % 81;
        C1s[nn * 84 + r] = C_local[(size_t)(node0 + nn) * 81 + r];
    }
    for (int q = tid; q < NB * 9; q += 160) {
        int nn = q / 9, i = q % 9;
        float s = 0.f;
#pragma unroll
        for (int k = 0; k < 9; k++) s += nbr_mask[(node0 + nn) * 9 + k];
        h1sh[nn * 9 + i] = nbr_mask[(node0 + nn) * 9 + i] / s;
    }
    __syncthreads();
    for (int q = tid; q < NB * 9; q += 160) {
        int nn = q / 9, i = q % 9;
        float s = 0.f;
#pragma unroll
        for (int k = 0; k < 9; k++) s += C1s[nn * 84 + i * 9 + k] * h1sh[nn * 9 + k];
        f1h1[nn * 9 + i] = s;
    }
    __syncthreads();

    // f2h2[m] = sum_k C2[m,k]^2 / 8 for this template
    float f2[8];
#pragma unroll
    for (int m = 0; m < 8; m++) {
        float s = 0.f;
#pragma unroll
        for (int k = 0; k < 8; k++) { float c = C2s[tpl * 64 + m * 8 + k]; s += c * c; }
        f2[m] = s * 0.125f;
    }

    // S = -5*(M + f1h1[i] + f2h2[m]) into shared, conflict-free [e][tid]
#pragma unroll
    for (int i = 0; i < 9; i++) {
        int id = idxs[nl * 9 + i];
        const float4* rp = (const float4*)(g_R + (size_t)id * 80 + tpl * 8);
        float4 r0 = rp[0], r1 = rp[1];
        float fi = f1h1[nl * 9 + i];
        Msh[(i * 8 + 0) * 160 + tid] = -5.f * (r0.x + fi + tns[tpl * 8 + 0] + f2[0]);
        Msh[(i * 8 + 1) * 160 + tid] = -5.f * (r0.y + fi + tns[tpl * 8 + 1] + f2[1]);
        Msh[(i * 8 + 2) * 160 + tid] = -5.f * (r0.z + fi + tns[tpl * 8 + 2] + f2[2]);
        Msh[(i * 8 + 3) * 160 + tid] = -5.f * (r0.w + fi + tns[tpl * 8 + 3] + f2[3]);
        Msh[(i * 8 + 4) * 160 + tid] = -5.f * (r1.x + fi + tns[tpl * 8 + 4] + f2[4]);
        Msh[(i * 8 + 5) * 160 + tid] = -5.f * (r1.y + fi + tns[tpl * 8 + 5] + f2[5]);
        Msh[(i * 8 + 6) * 160 + tid] = -5.f * (r1.z + fi + tns[tpl * 8 + 6] + f2[6]);
        Msh[(i * 8 + 7) * 160 + tid] = -5.f * (r1.w + fi + tns[tpl * 8 + 7] + f2[7]);
    }

    float h1r[9];
#pragma unroll
    for (int i = 0; i < 9; i++) h1r[i] = h1sh[nl * 9 + i];

    float A1[72], A2[72];
#pragma unroll
    for (int i = 0; i < 9; i++)
#pragma unroll
        for (int m = 0; m < 8; m++) A1[i * 8 + m] = h1r[i] * 0.125f;

#pragma unroll 1
    for (int outer = 0; outer < 3; outer++) {
        // A1 <- A1 @ C2 (row-wise in place)
#pragma unroll
        for (int i = 0; i < 9; i++) {
            float tmp[8];
#pragma unroll
            for (int m = 0; m < 8; m++) tmp[m] = 0.f;
#pragma unroll
            for (int k = 0; k < 8; k++) {
                float t = A1[i * 8 + k];
                float4 ca = *(const float4*)&C2s[tpl * 64 + k * 8];
                float4 cb = *(const float4*)&C2s[tpl * 64 + k * 8 + 4];
                tmp[0] += t * ca.x; tmp[1] += t * ca.y; tmp[2] += t * ca.z; tmp[3] += t * ca.w;
                tmp[4] += t * cb.x; tmp[5] += t * cb.y; tmp[6] += t * cb.z; tmp[7] += t * cb.w;
            }
#pragma unroll
            for (int m = 0; m < 8; m++) A1[i * 8 + m] = tmp[m];
        }
        // A2 = exp(S + 10 * (C1 @ A1))
#pragma unroll
        for (int i = 0; i < 9; i++) {
            float c1[9];
#pragma unroll
            for (int k = 0; k < 9; k++) c1[k] = C1s[nl * 84 + i * 9 + k];
#pragma unroll
            for (int m = 0; m < 8; m++) {
                float e = 0.f;
#pragma unroll
                for (int k = 0; k < 9; k++) e += c1[k] * A1[k * 8 + m];
                A2[i * 8 + m] = __expf(Msh[(i * 8 + m) * 160 + tid] + 10.f * e);
            }
        }
        // sinkhorn
        float v[8], u[9];
#pragma unroll
        for (int m = 0; m < 8; m++) v[m] = 1.f;
#pragma unroll 1
        for (int it = 0; it < 5; it++) {
#pragma unroll
            for (int i = 0; i < 9; i++) {
                float s = 1e-16f;
#pragma unroll
                for (int m = 0; m < 8; m++) s += A2[i * 8 + m] * v[m];
                u[i] = __fdividef(h1r[i], s);
            }
#pragma unroll
            for (int m = 0; m < 8; m++) {
                float s = 1e-16f;
#pragma unroll
                for (int i = 0; i < 9; i++) s += A2[i * 8 + m] * u[i];
                v[m] = __fdividef(0.125f, s);
            }
        }
#pragma unroll
        for (int i = 0; i < 9; i++)
#pragma unroll
            for (int m = 0; m < 8; m++) A1[i * 8 + m] = u[i] * A2[i * 8 + m] * v[m];
    }

    // final: A2 = A1 @ C2 ; obj = sum A1 * ( -S/10 - C1@A2 )
#pragma unroll
    for (int i = 0; i < 9; i++) {
#pragma unroll
        for (int m = 0; m < 8; m++) {
            float s = 0.f;
#pragma unroll
            for (int k = 0; k < 8; k++) s += A1[i * 8 + k] * C2s[tpl * 64 + k * 8 + m];
            A2[i * 8 + m] = s;
        }
    }
    float obj = 0.f;
#pragma unroll
    for (int i = 0; i < 9; i++) {
        float c1[9];
#pragma unroll
        for (int k = 0; k < 9; k++) c1[k] = C1s[nl * 84 + i * 9 + k];
#pragma unroll
        for (int m = 0; m < 8; m++) {
            float e = 0.f;
#pragma unroll
            for (int k = 0; k < 9; k++) e += c1[k] * A2[k * 8 + m];
            obj += A1[i * 8 + m] * (-0.1f * Msh[(i * 8 + m) * 160 + tid] - e);
        }
    }
    ysh[nl * 10 + tpl] = obj;
    __syncthreads();

    // head: out = relu(concat(h, y) @ Wlin + blin)
    if (tid < NB * NCLS) {
        int nn = tid / NCLS, c = tid % NCLS;
        float acc = blin[c];
#pragma unroll 8
        for (int k = 0; k < HID; k++)
            acc += h[(size_t)(node0 + nn) * HID + k] * Wlin[k * NCLS + c];
#pragma unroll
        for (int t = 0; t < NTPL; t++)
            acc += ysh[nn * 10 + t] * Wlin[(HID + t) * NCLS + c];
        out[(node0 + nn) * NCLS + c] = fmaxf(acc, 0.f);
    }
}

// ---------------- launch ----------------
extern "C" void kernel_launch(void* const* d_in, const int* in_sizes, int n_in,
                              void* d_out, int out_size)
{
    const float* x     = (const float*)d_in[0];
    const int*   ei    = (const int*)  d_in[1];
    const int*   nbr   = (const int*)  d_in[2];
    const float* mask  = (const float*)d_in[3];
    const float* Cl    = (const float*)d_in[4];
    const float* W1    = (const float*)d_in[5];
    const float* b1    = (const float*)d_in[6];
    const float* W2    = (const float*)d_in[7];
    const float* b2    = (const float*)d_in[8];
    const float* tadj  = (const float*)d_in[9];
    const float* tfeat = (const float*)d_in[10];
    const float* Wlin  = (const float*)d_in[11];
    const float* blin  = (const float*)d_in[12];
    float* out = (float*)d_out;

    const int* src = ei;
    const int* dst = ei + EE;

    void *pA, *pB, *pC;
    cudaGetSymbolAddress(&pA, g_bufA);
    cudaGetSymbolAddress(&pB, g_bufB);
    cudaGetSymbolAddress(&pC, g_bufC);
    float* bufA = (float*)pA;
    float* bufB = (float*)pB;
    float* bufC = (float*)pC;

    const int dist_smem = (72 * 160 + NB * 84 + NB * 9 * 2 + 640 + NB * 10 + 80 + NB * 9) * 4;
    cudaFuncSetAttribute(k_dist, cudaFuncAttributeMaxDynamicSharedMemorySize, dist_smem);

    // CSR build + dinv
    k_zero <<<(NN + 255) / 256, 256>>>();
    k_count<<<(EE + 255) / 256, 256>>>(dst);
    k_dinv <<<(NN + 255) / 256, 256>>>();
    k_scan <<<1, 1024>>>();
    k_fill <<<(EE + 255) / 256, 256>>>(src, dst);

    // layer 1
    k_gemm<false><<<(NN + 63) / 64, 128>>>(x, W1, b1, bufA, bufB, NN, FIN, FIN);
    k_gather<<<NN / 4, 256>>>(bufA, bufB);

    // layer 2
    k_gemm<true><<<(NN + 63) / 64, 128>>>(bufB, W2, b2, bufA, bufC, NN, HID, HID);
    k_gather<<<NN / 4, 256>>>(bufA, bufC);

    // cost precompute
    k_tn<<<1, 128>>>(tfeat);
    k_pr<<<(NN + 63) / 64, 256>>>(bufC, tfeat);

    // FGW + head
    k_dist<<<NN / NB, 160, dist_smem>>>(bufC, nbr, mask, Cl, tadj, Wlin, blin, out);
}

// round 4
// speedup vs baseline: 1.8814x; 1.1491x over previous
#include <cuda_runtime.h>
#include <cstdint>

#define NN   20000
#define EE   320000
#define FIN  512
#define HID  64
#define LL   9
#define NTPL 10
#define NTN  8
#define NCLS 6
#define NB   16      // nodes per k_dist block
#define SLOT 64      // max in-degree bucket

// -------- scratch (no cudaMalloc allowed) --------
__device__ float g_bufA[NN * HID];
__device__ float g_bufB[NN * HID];
__device__ float g_bufC[NN * HID];
__device__ float g_dinv[NN];
__device__ int   g_cnt[NN];
__device__ int   g_csrc[NN * SLOT];
__device__ float g_R[NN * 80];     // ||h||^2 + ||f||^2 - 2 h@f^T

// ---------------- bucket fill + dinv ----------------
__global__ void k_fill(const int* __restrict__ src, const int* __restrict__ dst) {
    int e = blockIdx.x * blockDim.x + threadIdx.x;
    if (e < EE) {
        int d = dst[e];
        int slot = atomicAdd(&g_cnt[d], 1);
        g_csrc[d * SLOT + slot] = src[e];
    }
}
__global__ void k_dinv() {
    int i = blockIdx.x * blockDim.x + threadIdx.x;
    if (i < NN) g_dinv[i] = rsqrtf((float)g_cnt[i] + 1.0f);
}

// ---------------- cp.async helpers ----------------
__device__ __forceinline__ void cp16(uint32_t sdst, const void* gsrc, bool pred) {
    int sz = pred ? 16 : 0;
    asm volatile("cp.async.cg.shared.global [%0], [%1], 16, %2;\n"
                 :: "r"(sdst), "l"(gsrc), "r"(sz));
}
__device__ __forceinline__ void cp_commit() {
    asm volatile("cp.async.commit_group;\n");
}
template <int N>
__device__ __forceinline__ void cp_wait() {
    asm volatile("cp.async.wait_group %0;\n" :: "n"(N));
}

// ---------------- GEMM: oXW = (A[M,K] @ W[K,64]) * dinv[row]  (double-buffered) ----------------
#define AS_STRIDE 68
#define AS_TILE  (64 * AS_STRIDE)
#define BS_TILE  (64 * 64)
#define GEMM_SMEM ((2 * AS_TILE + 2 * BS_TILE) * 4)

__global__ __launch_bounds__(128) void k_gemm(
    const float* __restrict__ A, const float* __restrict__ W,
    float* __restrict__ oXW, int M, int K, int lda)
{
    extern __shared__ float smem[];
    float* As = smem;                  // [2][64][AS_STRIDE]
    float* Bs = smem + 2 * AS_TILE;    // [2][64][64]
    const uint32_t sAs = (uint32_t)__cvta_generic_to_shared(As);
    const uint32_t sBs = (uint32_t)__cvta_generic_to_shared(Bs);

    const int t  = threadIdx.x;
    const int tx = t & 15, ty = t >> 4;      // ty: 8 rows each; tx: 4 cols
    const int row0 = blockIdx.x * 64;

    float acc[8][4];
#pragma unroll
    for (int i = 0; i < 8; i++)
#pragma unroll
        for (int c = 0; c < 4; c++) acc[i][c] = 0.f;

    // issue tile 0
#pragma unroll
    for (int p = 0; p < 8; p++) {
        int v = t + 128 * p;
        int r = v >> 4, c4 = v & 15;
        int gr = row0 + r;
        cp16(sAs + (r * AS_STRIDE + c4 * 4) * 4,
             A + (size_t)gr * lda + c4 * 4, gr < M);
    }
#pragma unroll
    for (int p = 0; p < 8; p++) {
        int v = t + 128 * p;
        int r = v >> 4, c4 = v & 15;
        cp16(sBs + (r * 64 + c4 * 4) * 4,
             W + (size_t)r * HID + c4 * 4, true);
    }
    cp_commit();

    int buf = 0;
    for (int kt = 0; kt < K; kt += 64, buf ^= 1) {
        if (kt + 64 < K) {
            int nb = buf ^ 1;
#pragma unroll
            for (int p = 0; p < 8; p++) {
                int v = t + 128 * p;
                int r = v >> 4, c4 = v & 15;
                int gr = row0 + r;
                cp16(sAs + (nb * AS_TILE + r * AS_STRIDE + c4 * 4) * 4,
                     A + (size_t)gr * lda + kt + 64 + c4 * 4, gr < M);
            }
#pragma unroll
            for (int p = 0; p < 8; p++) {
                int v = t + 128 * p;
                int r = v >> 4, c4 = v & 15;
                cp16(sBs + (nb * BS_TILE + r * 64 + c4 * 4) * 4,
                     W + (size_t)(kt + 64 + r) * HID + c4 * 4, true);
            }
            cp_commit();
            cp_wait<1>();
        } else {
            cp_wait<0>();
        }
        __syncthreads();

        const float* Ab = As + buf * AS_TILE;
        const float* Bb = Bs + buf * BS_TILE;
#pragma unroll
        for (int k = 0; k < 64; k += 4) {
            float4 a4[8], b4[4];
#pragma unroll
            for (int i = 0; i < 8; i++) a4[i] = *(const float4*)&Ab[(ty * 8 + i) * AS_STRIDE + k];
#pragma unroll
            for (int kk = 0; kk < 4; kk++) b4[kk] = *(const float4*)&Bb[(k + kk) * 64 + tx * 4];
#pragma unroll
            for (int i = 0; i < 8; i++) {
                acc[i][0] += a4[i].x*b4[0].x + a4[i].y*b4[1].x + a4[i].z*b4[2].x + a4[i].w*b4[3].x;
                acc[i][1] += a4[i].x*b4[0].y + a4[i].y*b4[1].y + a4[i].z*b4[2].y + a4[i].w*b4[3].y;
                acc[i][2] += a4[i].x*b4[0].z + a4[i].y*b4[1].z + a4[i].z*b4[2].z + a4[i].w*b4[3].z;
                acc[i][3] += a4[i].x*b4[0].w + a4[i].y*b4[1].w + a4[i].z*b4[2].w + a4[i].w*b4[3].w;
            }
        }
        __syncthreads();
    }
#pragma unroll
    for (int i = 0; i < 8; i++) {
        int gr = row0 + ty * 8 + i;
        if (gr < M) {
            float dv = g_dinv[gr];
#pragma unroll
            for (int c = 0; c < 4; c++)
                oXW[(size_t)gr * HID + tx * 4 + c] = acc[i][c] * dv;
        }
    }
}

// ---------------- gather: h[d] = act( bias + dinv[d] * (xws[d] + sum_in xws[s]) ) ----------------
template <bool RELU>
__global__ __launch_bounds__(256) void k_gather(
    const float* __restrict__ xws, const float* __restrict__ bias,
    float* __restrict__ h)
{
    int d = blockIdx.x * 4 + (threadIdx.x >> 6);
    int f = threadIdx.x & 63;
    if (d >= NN) return;
    int cnt = g_cnt[d];
    const int* lst = g_csrc + (size_t)d * SLOT;
    float acc = xws[(size_t)d * HID + f];   // self (already scaled by dinv[d])
    int e = 0;
    for (; e + 1 < cnt; e += 2) {
        int sa = lst[e], sb = lst[e + 1];
        acc += xws[(size_t)sa * HID + f] + xws[(size_t)sb * HID + f];
    }
    if (e < cnt) acc += xws[(size_t)lst[e] * HID + f];
    acc = acc * g_dinv[d] + bias[f];
    h[(size_t)d * HID + f] = RELU ? fmaxf(acc, 0.f) : acc;
}

// ---------------- R = ||h||^2 + ||f||^2 - 2 * h @ tfeat^T : [NN, 80] ----------------
__global__ __launch_bounds__(256) void k_pr(
    const float* __restrict__ h, const float* __restrict__ tfeat)
{
    __shared__ float hs[64][68];    // 272B row stride: float4 aligned
    __shared__ float tfs[64][81];   // transposed [k][tm]
    __shared__ float tnl[80];
    const int t = threadIdx.x;
    const int r0 = blockIdx.x * 64;
#pragma unroll
    for (int p = 0; p < 4; p++) {
        int v = t + 256 * p;
        int r = v >> 4, c4 = v & 15;
        int gr = r0 + r;
        float4 val = make_float4(0.f, 0.f, 0.f, 0.f);
        if (gr < NN) val = *(const float4*)(h + (size_t)gr * HID + c4 * 4);
        *(float4*)&hs[r][c4 * 4] = val;
    }
    for (int q = t; q < 80 * 64; q += 256) {
        int tm = q >> 6, k = q & 63;
        tfs[k][tm] = tfeat[q];
    }
    __syncthreads();
    if (t < 80) {
        float s = 0.f;
#pragma unroll
        for (int k = 0; k < 64; k++) { float v = tfs[k][t]; s += v * v; }
        tnl[t] = s;
    }
    __syncthreads();
    const int ty = t >> 4, tx = t & 15;  // 4 rows, 5 cols
    float acc[4][5];
    float h2[4];
#pragma unroll
    for (int i = 0; i < 4; i++) { h2[i] = 0.f;
#pragma unroll
        for (int c = 0; c < 5; c++) acc[i][c] = 0.f; }
#pragma unroll
    for (int k = 0; k < 64; k++) {
        float a[4], b[5];
#pragma unroll
        for (int i = 0; i < 4; i++) a[i] = hs[ty * 4 + i][k];
#pragma unroll
        for (int c = 0; c < 5; c++) b[c] = tfs[k][tx * 5 + c];
#pragma unroll
        for (int i = 0; i < 4; i++) {
            h2[i] += a[i] * a[i];
#pragma unroll
            for (int c = 0; c < 5; c++) acc[i][c] += a[i] * b[c];
        }
    }
#pragma unroll
    for (int i = 0; i < 4; i++) {
        int gr = r0 + ty * 4 + i;
        if (gr < NN) {
#pragma unroll
            for (int c = 0; c < 5; c++)
                g_R[(size_t)gr * 80 + tx * 5 + c] = h2[i] + tnl[tx * 5 + c] - 2.f * acc[i][c];
        }
    }
}

// ---------------- FGW distances (scalar per node x template) + linear head ----------------
__global__ __launch_bounds__(160, 2) void k_dist(
    const float* __restrict__ h,
    const int*   __restrict__ nbr_idx,
    const float* __restrict__ nbr_mask,
    const float* __restrict__ C_local,
    const float* __restrict__ tadj,     // [10,8,8]
    const float* __restrict__ Wlin,     // [74,6]
    const float* __restrict__ blin,
    float* __restrict__ out)
{
    extern __shared__ float sm[];
    float* Msh  = sm;                     // [72][160]  S = -5*(M + constC)
    float* C1s  = Msh  + 72 * 160;        // [NB][84]
    float* h1sh = C1s  + NB * 84;         // [NB][9]
    float* f1h1 = h1sh + NB * 9;          // [NB][9]
    float* C2s  = f1h1 + NB * 9;          // [10][64]
    float* ysh  = C2s  + 640;             // [NB][10]
    int*   idxs = (int*)(ysh + NB * 10);  // [NB][9]

    const int tid = threadIdx.x;
    const int nl  = tid / 10;
    const int tpl = tid % 10;
    const int node0 = blockIdx.x * NB;

    for (int q = tid; q < 640; q += 160) C2s[q] = tadj[q];
    for (int q = tid; q < NB * 9; q += 160) {
        int nn = q / 9, i = q % 9;
        idxs[nn * 9 + i] = (i == 0) ? (node0 + nn) : nbr_idx[(node0 + nn) * 8 + i - 1];
    }
    for (int q = tid; q < NB * 81; q += 160) {
        int nn = q / 81, r = q % 81;
        C1s[nn * 84 + r] = C_local[(size_t)(node0 + nn) * 81 + r];
    }
    for (int q = tid; q < NB * 9; q += 160) {
        int nn = q / 9, i = q % 9;
        float s = 0.f;
#pragma unroll
        for (int k = 0; k < 9; k++) s += nbr_mask[(node0 + nn) * 9 + k];
        h1sh[nn * 9 + i] = nbr_mask[(node0 + nn) * 9 + i] / s;
    }
    __syncthreads();
    for (int q = tid; q < NB * 9; q += 160) {
        int nn = q / 9, i = q % 9;
        float s = 0.f;
#pragma unroll
        for (int k = 0; k < 9; k++) s += C1s[nn * 84 + i * 9 + k] * h1sh[nn * 9 + k];
        f1h1[nn * 9 + i] = s;
    }
    __syncthreads();

    // f2h2[m] = sum_k C2[m,k]^2 / 8 for this template
    float f2[8];
#pragma unroll
    for (int m = 0; m < 8; m++) {
        float s = 0.f;
#pragma unroll
        for (int k = 0; k < 8; k++) { float c = C2s[tpl * 64 + m * 8 + k]; s += c * c; }
        f2[m] = s * 0.125f;
    }

    // S = -5*(R + f1h1[i] + f2h2[m]) into shared, conflict-free [e][tid]
#pragma unroll
    for (int i = 0; i < 9; i++) {
        int id = idxs[nl * 9 + i];
        const float4* rp = (const float4*)(g_R + (size_t)id * 80 + tpl * 8);
        float4 r0 = rp[0], r1 = rp[1];
        float fi = f1h1[nl * 9 + i];
        Msh[(i * 8 + 0) * 160 + tid] = -5.f * (r0.x + fi + f2[0]);
        Msh[(i * 8 + 1) * 160 + tid] = -5.f * (r0.y + fi + f2[1]);
        Msh[(i * 8 + 2) * 160 + tid] = -5.f * (r0.z + fi + f2[2]);
        Msh[(i * 8 + 3) * 160 + tid] = -5.f * (r0.w + fi + f2[3]);
        Msh[(i * 8 + 4) * 160 + tid] = -5.f * (r1.x + fi + f2[4]);
        Msh[(i * 8 + 5) * 160 + tid] = -5.f * (r1.y + fi + f2[5]);
        Msh[(i * 8 + 6) * 160 + tid] = -5.f * (r1.z + fi + f2[6]);
        Msh[(i * 8 + 7) * 160 + tid] = -5.f * (r1.w + fi + f2[7]);
    }

    float h1r[9];
#pragma unroll
    for (int i = 0; i < 9; i++) h1r[i] = h1sh[nl * 9 + i];

    float A1[72], A2[72];
#pragma unroll
    for (int i = 0; i < 9; i++)
#pragma unroll
        for (int m = 0; m < 8; m++) A1[i * 8 + m] = h1r[i] * 0.125f;

#pragma unroll 1
    for (int outer = 0; outer < 3; outer++) {
        // A1 <- A1 @ C2 (row-wise in place)
#pragma unroll
        for (int i = 0; i < 9; i++) {
            float tmp[8];
#pragma unroll
            for (int m = 0; m < 8; m++) tmp[m] = 0.f;
#pragma unroll
            for (int k = 0; k < 8; k++) {
                float t = A1[i * 8 + k];
                float4 ca = *(const float4*)&C2s[tpl * 64 + k * 8];
                float4 cb = *(const float4*)&C2s[tpl * 64 + k * 8 + 4];
                tmp[0] += t * ca.x; tmp[1] += t * ca.y; tmp[2] += t * ca.z; tmp[3] += t * ca.w;
                tmp[4] += t * cb.x; tmp[5] += t * cb.y; tmp[6] += t * cb.z; tmp[7] += t * cb.w;
            }
#pragma unroll
            for (int m = 0; m < 8; m++) A1[i * 8 + m] = tmp[m];
        }
        // A2 = exp(S + 10 * (C1 @ A1))
#pragma unroll
        for (int i = 0; i < 9; i++) {
            float c1[9];
#pragma unroll
            for (int k = 0; k < 9; k++) c1[k] = C1s[nl * 84 + i * 9 + k];
#pragma unroll
            for (int m = 0; m < 8; m++) {
                float e = 0.f;
#pragma unroll
                for (int k = 0; k < 9; k++) e += c1[k] * A1[k * 8 + m];
                A2[i * 8 + m] = __expf(Msh[(i * 8 + m) * 160 + tid] + 10.f * e);
            }
        }
        // sinkhorn
        float v[8], u[9];
#pragma unroll
        for (int m = 0; m < 8; m++) v[m] = 1.f;
#pragma unroll 1
        for (int it = 0; it < 5; it++) {
#pragma unroll
            for (int i = 0; i < 9; i++) {
                float s = 1e-16f;
#pragma unroll
                for (int m = 0; m < 8; m++) s += A2[i * 8 + m] * v[m];
                u[i] = __fdividef(h1r[i], s);
            }
#pragma unroll
            for (int m = 0; m < 8; m++) {
                float s = 1e-16f;
#pragma unroll
                for (int i = 0; i < 9; i++) s += A2[i * 8 + m] * u[i];
                v[m] = __fdividef(0.125f, s);
            }
        }
#pragma unroll
        for (int i = 0; i < 9; i++)
#pragma unroll
            for (int m = 0; m < 8; m++) A1[i * 8 + m] = u[i] * A2[i * 8 + m] * v[m];
    }

    // final: A2 = A1 @ C2 ; obj = sum A1 * ( -S/10 - C1@A2 )
#pragma unroll
    for (int i = 0; i < 9; i++) {
#pragma unroll
        for (int m = 0; m < 8; m++) {
            float s = 0.f;
#pragma unroll
            for (int k = 0; k < 8; k++) s += A1[i * 8 + k] * C2s[tpl * 64 + k * 8 + m];
            A2[i * 8 + m] = s;
        }
    }
    float obj = 0.f;
#pragma unroll
    for (int i = 0; i < 9; i++) {
        float c1[9];
#pragma unroll
        for (int k = 0; k < 9; k++) c1[k] = C1s[nl * 84 + i * 9 + k];
#pragma unroll
        for (int m = 0; m < 8; m++) {
            float e = 0.f;
#pragma unroll
            for (int k = 0; k < 9; k++) e += c1[k] * A2[k * 8 + m];
            obj += A1[i * 8 + m] * (-0.1f * Msh[(i * 8 + m) * 160 + tid] - e);
        }
    }
    ysh[nl * 10 + tpl] = obj;
    __syncthreads();

    // head: out = relu(concat(h, y) @ Wlin + blin)
    if (tid < NB * NCLS) {
        int nn = tid / NCLS, c = tid % NCLS;
        float acc = blin[c];
#pragma unroll 8
        for (int k = 0; k < HID; k++)
            acc += h[(size_t)(node0 + nn) * HID + k] * Wlin[k * NCLS + c];
#pragma unroll
        for (int t = 0; t < NTPL; t++)
            acc += ysh[nn * 10 + t] * Wlin[(HID + t) * NCLS + c];
        out[(node0 + nn) * NCLS + c] = fmaxf(acc, 0.f);
    }
}

// ---------------- launch ----------------
extern "C" void kernel_launch(void* const* d_in, const int* in_sizes, int n_in,
                              void* d_out, int out_size)
{
    const float* x     = (const float*)d_in[0];
    const int*   ei    = (const int*)  d_in[1];
    const int*   nbr   = (const int*)  d_in[2];
    const float* mask  = (const float*)d_in[3];
    const float* Cl    = (const float*)d_in[4];
    const float* W1    = (const float*)d_in[5];
    const float* b1    = (const float*)d_in[6];
    const float* W2    = (const float*)d_in[7];
    const float* b2    = (const float*)d_in[8];
    const float* tadj  = (const float*)d_in[9];
    const float* tfeat = (const float*)d_in[10];
    const float* Wlin  = (const float*)d_in[11];
    const float* blin  = (const float*)d_in[12];
    float* out = (float*)d_out;

    const int* src = ei;
    const int* dst = ei + EE;

    void *pA, *pB, *pC, *pCnt;
    cudaGetSymbolAddress(&pA, g_bufA);
    cudaGetSymbolAddress(&pB, g_bufB);
    cudaGetSymbolAddress(&pC, g_bufC);
    cudaGetSymbolAddress(&pCnt, g_cnt);
    float* bufA = (float*)pA;
    float* bufB = (float*)pB;
    float* bufC = (float*)pC;

    const int dist_smem = (72 * 160 + NB * 84 + NB * 9 * 2 + 640 + NB * 10 + NB * 9) * 4;
    cudaFuncSetAttribute(k_dist, cudaFuncAttributeMaxDynamicSharedMemorySize, dist_smem);
    cudaFuncSetAttribute(k_gemm, cudaFuncAttributeMaxDynamicSharedMemorySize, GEMM_SMEM);

    // bucket build + dinv
    cudaMemsetAsync(pCnt, 0, NN * sizeof(int));
    k_fill<<<(EE + 255) / 256, 256>>>(src, dst);
    k_dinv<<<(NN + 255) / 256, 256>>>();

    // layer 1
    k_gemm<<<(NN + 63) / 64, 128, GEMM_SMEM>>>(x, W1, bufA, NN, FIN, FIN);
    k_gather<true><<<NN / 4, 256>>>(bufA, b1, bufB);

    // layer 2
    k_gemm<<<(NN + 63) / 64, 128, GEMM_SMEM>>>(bufB, W2, bufA, NN, HID, HID);
    k_gather<false><<<NN / 4, 256>>>(bufA, b2, bufC);

    // cost precompute
    k_pr<<<(NN + 63) / 64, 256>>>(bufC, tfeat);

    // FGW + head
    k_dist<<<NN / NB, 160, dist_smem>>>(bufC, nbr, mask, Cl, tadj, Wlin, blin, out);
}

// round 5
// speedup vs baseline: 2.2652x; 1.2040x over previous
#include <cuda_runtime.h>
#include <cstdint>

#define NN   20000
#define EE   320000
#define FIN  512
#define HID  64
#define LL   9
#define NTPL 10
#define NTN  8
#define NCLS 6
#define NB   16      // nodes per k_dist block
#define SLOT 64      // max in-degree bucket

typedef unsigned long long u64;

// -------- scratch (no cudaMalloc allowed) --------
__device__ float g_bufA[NN * HID];
__device__ float g_bufB[NN * HID];
__device__ float g_bufC[NN * HID];
__device__ float g_dinv[NN];
__device__ int   g_cnt[NN];
__device__ int   g_csrc[NN * SLOT];
__device__ float g_R[NN * 80];     // ||h||^2 + ||f||^2 - 2 h@f^T

// ---------------- f32x2 packed helpers ----------------
__device__ __forceinline__ u64 pk2(float lo, float hi) {
    u64 r; asm("mov.b64 %0,{%1,%2};" : "=l"(r) : "f"(lo), "f"(hi)); return r;
}
__device__ __forceinline__ u64 pk1(float x) {
    u64 r; asm("mov.b64 %0,{%1,%1};" : "=l"(r) : "f"(x)); return r;
}
__device__ __forceinline__ void upk(u64 v, float& lo, float& hi) {
    asm("mov.b64 {%0,%1},%2;" : "=f"(lo), "=f"(hi) : "l"(v));
}
__device__ __forceinline__ u64 fma2(u64 a, u64 b, u64 c) {
    u64 d; asm("fma.rn.f32x2 %0,%1,%2,%3;" : "=l"(d) : "l"(a), "l"(b), "l"(c)); return d;
}
__device__ __forceinline__ u64 mul2(u64 a, u64 b) {
    u64 d; asm("mul.rn.f32x2 %0,%1,%2;" : "=l"(d) : "l"(a), "l"(b)); return d;
}
__device__ __forceinline__ u64 add2(u64 a, u64 b) {
    u64 d; asm("add.rn.f32x2 %0,%1,%2;" : "=l"(d) : "l"(a), "l"(b)); return d;
}

// ---------------- bucket fill + dinv ----------------
__global__ void k_fill(const int* __restrict__ src, const int* __restrict__ dst) {
    int e = blockIdx.x * blockDim.x + threadIdx.x;
    if (e < EE) {
        int d = dst[e];
        int slot = atomicAdd(&g_cnt[d], 1);
        g_csrc[d * SLOT + slot] = src[e];
    }
}
__global__ void k_dinv() {
    int i = blockIdx.x * blockDim.x + threadIdx.x;
    if (i < NN) g_dinv[i] = rsqrtf((float)g_cnt[i] + 1.0f);
}

// ---------------- cp.async helpers ----------------
__device__ __forceinline__ void cp16(uint32_t sdst, const void* gsrc, bool pred) {
    int sz = pred ? 16 : 0;
    asm volatile("cp.async.cg.shared.global [%0], [%1], 16, %2;\n"
                 :: "r"(sdst), "l"(gsrc), "r"(sz));
}
__device__ __forceinline__ void cp_commit() {
    asm volatile("cp.async.commit_group;\n");
}
template <int N>
__device__ __forceinline__ void cp_wait() {
    asm volatile("cp.async.wait_group %0;\n" :: "n"(N));
}

// ---------------- GEMM: oXW = (A[M,K] @ W[K,64]) * dinv[row]  (double-buffered) ----------------
#define AS_STRIDE 68
#define AS_TILE  (64 * AS_STRIDE)
#define BS_TILE  (64 * 64)
#define GEMM_SMEM ((2 * AS_TILE + 2 * BS_TILE) * 4)

__global__ __launch_bounds__(128) void k_gemm(
    const float* __restrict__ A, const float* __restrict__ W,
    float* __restrict__ oXW, int M, int K, int lda)
{
    extern __shared__ float smem[];
    float* As = smem;                  // [2][64][AS_STRIDE]
    float* Bs = smem + 2 * AS_TILE;    // [2][64][64]
    const uint32_t sAs = (uint32_t)__cvta_generic_to_shared(As);
    const uint32_t sBs = (uint32_t)__cvta_generic_to_shared(Bs);

    const int t  = threadIdx.x;
    const int tx = t & 15, ty = t >> 4;
    const int row0 = blockIdx.x * 64;

    float acc[8][4];
#pragma unroll
    for (int i = 0; i < 8; i++)
#pragma unroll
        for (int c = 0; c < 4; c++) acc[i][c] = 0.f;

#pragma unroll
    for (int p = 0; p < 8; p++) {
        int v = t + 128 * p;
        int r = v >> 4, c4 = v & 15;
        int gr = row0 + r;
        cp16(sAs + (r * AS_STRIDE + c4 * 4) * 4,
             A + (size_t)gr * lda + c4 * 4, gr < M);
    }
#pragma unroll
    for (int p = 0; p < 8; p++) {
        int v = t + 128 * p;
        int r = v >> 4, c4 = v & 15;
        cp16(sBs + (r * 64 + c4 * 4) * 4,
             W + (size_t)r * HID + c4 * 4, true);
    }
    cp_commit();

    int buf = 0;
    for (int kt = 0; kt < K; kt += 64, buf ^= 1) {
        if (kt + 64 < K) {
            int nb = buf ^ 1;
#pragma unroll
            for (int p = 0; p < 8; p++) {
                int v = t + 128 * p;
                int r = v >> 4, c4 = v & 15;
                int gr = row0 + r;
                cp16(sAs + (nb * AS_TILE + r * AS_STRIDE + c4 * 4) * 4,
                     A + (size_t)gr * lda + kt + 64 + c4 * 4, gr < M);
            }
#pragma unroll
            for (int p = 0; p < 8; p++) {
                int v = t + 128 * p;
                int r = v >> 4, c4 = v & 15;
                cp16(sBs + (nb * BS_TILE + r * 64 + c4 * 4) * 4,
                     W + (size_t)(kt + 64 + r) * HID + c4 * 4, true);
            }
            cp_commit();
            cp_wait<1>();
        } else {
            cp_wait<0>();
        }
        __syncthreads();

        const float* Ab = As + buf * AS_TILE;
        const float* Bb = Bs + buf * BS_TILE;
#pragma unroll
        for (int k = 0; k < 64; k += 4) {
            float4 a4[8], b4[4];
#pragma unroll
            for (int i = 0; i < 8; i++) a4[i] = *(const float4*)&Ab[(ty * 8 + i) * AS_STRIDE + k];
#pragma unroll
            for (int kk = 0; kk < 4; kk++) b4[kk] = *(const float4*)&Bb[(k + kk) * 64 + tx * 4];
#pragma unroll
            for (int i = 0; i < 8; i++) {
                acc[i][0] += a4[i].x*b4[0].x + a4[i].y*b4[1].x + a4[i].z*b4[2].x + a4[i].w*b4[3].x;
                acc[i][1] += a4[i].x*b4[0].y + a4[i].y*b4[1].y + a4[i].z*b4[2].y + a4[i].w*b4[3].y;
                acc[i][2] += a4[i].x*b4[0].z + a4[i].y*b4[1].z + a4[i].z*b4[2].z + a4[i].w*b4[3].z;
                acc[i][3] += a4[i].x*b4[0].w + a4[i].y*b4[1].w + a4[i].z*b4[2].w + a4[i].w*b4[3].w;
            }
        }
        __syncthreads();
    }
#pragma unroll
    for (int i = 0; i < 8; i++) {
        int gr = row0 + ty * 8 + i;
        if (gr < M) {
            float dv = g_dinv[gr];
#pragma unroll
            for (int c = 0; c < 4; c++)
                oXW[(size_t)gr * HID + tx * 4 + c] = acc[i][c] * dv;
        }
    }
}

// ---------------- gather: h[d] = act( bias + dinv[d] * (xws[d] + sum_in xws[s]) ) ----------------
template <bool RELU>
__global__ __launch_bounds__(256) void k_gather(
    const float* __restrict__ xws, const float* __restrict__ bias,
    float* __restrict__ h)
{
    int d = blockIdx.x * 4 + (threadIdx.x >> 6);
    int f = threadIdx.x & 63;
    if (d >= NN) return;
    int cnt = g_cnt[d];
    const int* lst = g_csrc + (size_t)d * SLOT;
    float a0 = xws[(size_t)d * HID + f];   // self (already scaled by dinv[d])
    float a1 = 0.f, a2 = 0.f, a3 = 0.f;
    int e = 0;
    for (; e + 3 < cnt; e += 4) {
        int s0 = lst[e], s1 = lst[e + 1], s2 = lst[e + 2], s3 = lst[e + 3];
        a0 += xws[(size_t)s0 * HID + f];
        a1 += xws[(size_t)s1 * HID + f];
        a2 += xws[(size_t)s2 * HID + f];
        a3 += xws[(size_t)s3 * HID + f];
    }
    for (; e < cnt; e++) a0 += xws[(size_t)lst[e] * HID + f];
    float acc = ((a0 + a1) + (a2 + a3)) * g_dinv[d] + bias[f];
    h[(size_t)d * HID + f] = RELU ? fmaxf(acc, 0.f) : acc;
}

// ---------------- R = ||h||^2 + ||f||^2 - 2 * h @ tfeat^T : [NN, 80] ----------------
__global__ __launch_bounds__(256) void k_pr(
    const float* __restrict__ h, const float* __restrict__ tfeat)
{
    __shared__ float hs[64][68];
    __shared__ float tfs[64][81];
    __shared__ float tnl[80];
    const int t = threadIdx.x;
    const int r0 = blockIdx.x * 64;
#pragma unroll
    for (int p = 0; p < 4; p++) {
        int v = t + 256 * p;
        int r = v >> 4, c4 = v & 15;
        int gr = r0 + r;
        float4 val = make_float4(0.f, 0.f, 0.f, 0.f);
        if (gr < NN) val = *(const float4*)(h + (size_t)gr * HID + c4 * 4);
        *(float4*)&hs[r][c4 * 4] = val;
    }
    for (int q = t; q < 80 * 64; q += 256) {
        int tm = q >> 6, k = q & 63;
        tfs[k][tm] = tfeat[q];
    }
    __syncthreads();
    if (t < 80) {
        float s = 0.f;
#pragma unroll
        for (int k = 0; k < 64; k++) { float v = tfs[k][t]; s += v * v; }
        tnl[t] = s;
    }
    __syncthreads();
    const int ty = t >> 4, tx = t & 15;
    float acc[4][5];
    float h2[4];
#pragma unroll
    for (int i = 0; i < 4; i++) { h2[i] = 0.f;
#pragma unroll
        for (int c = 0; c < 5; c++) acc[i][c] = 0.f; }
#pragma unroll
    for (int k = 0; k < 64; k++) {
        float a[4], b[5];
#pragma unroll
        for (int i = 0; i < 4; i++) a[i] = hs[ty * 4 + i][k];
#pragma unroll
        for (int c = 0; c < 5; c++) b[c] = tfs[k][tx * 5 + c];
#pragma unroll
        for (int i = 0; i < 4; i++) {
            h2[i] += a[i] * a[i];
#pragma unroll
            for (int c = 0; c < 5; c++) acc[i][c] += a[i] * b[c];
        }
    }
#pragma unroll
    for (int i = 0; i < 4; i++) {
        int gr = r0 + ty * 4 + i;
        if (gr < NN) {
#pragma unroll
            for (int c = 0; c < 5; c++)
                g_R[(size_t)gr * 80 + tx * 5 + c] = h2[i] + tnl[tx * 5 + c] - 2.f * acc[i][c];
        }
    }
}

// ---------------- FGW distances (packed f32x2, 1 thread per node x template) ----------------
#define DIST_SMEM (5760*8 + (NB*81)*8 + 320*8 + (NB*9)*4*2 + (NB*10)*4 + (NB*9)*4)

__global__ __launch_bounds__(160, 2) void k_dist(
    const float* __restrict__ h,
    const int*   __restrict__ nbr_idx,
    const float* __restrict__ nbr_mask,
    const float* __restrict__ C_local,
    const float* __restrict__ tadj,     // [10,8,8]
    const float* __restrict__ Wlin,     // [74,6]
    const float* __restrict__ blin,
    float* __restrict__ out)
{
    extern __shared__ __align__(16) unsigned char smraw[];
    u64*   Msh2 = (u64*)smraw;            // [36][160]  packed S = -5*(R + constC)
    u64*   C1p  = Msh2 + 36 * 160;        // [NB][81]   C1 entries broadcast-packed
    u64*   C2p  = C1p + NB * 81;          // [10][8][4] C2 rows k, lanes m
    float* h1sh = (float*)(C2p + 320);    // [NB][9]
    float* f1h1 = h1sh + NB * 9;          // [NB][9]
    float* ysh  = f1h1 + NB * 9;          // [NB][10]
    int*   idxs = (int*)(ysh + NB * 10);  // [NB][9]

    const int tid = threadIdx.x;
    const int nl  = tid / 10;
    const int tpl = tid % 10;
    const int node0 = blockIdx.x * NB;

    // ---- cooperative setup ----
    for (int q = tid; q < 320; q += 160)
        C2p[q] = pk2(tadj[2 * q], tadj[2 * q + 1]);
    for (int q = tid; q < NB * 9; q += 160) {
        int nn = q / 9, i = q % 9;
        idxs[nn * 9 + i] = (i == 0) ? (node0 + nn) : nbr_idx[(node0 + nn) * 8 + i - 1];
    }
    for (int q = tid; q < NB * 81; q += 160) {
        int nn = q / 81, r = q % 81;
        C1p[nn * 81 + r] = pk1(C_local[(size_t)(node0 + nn) * 81 + r]);
    }
    for (int q = tid; q < NB * 9; q += 160) {
        int nn = q / 9, i = q % 9;
        float s = 0.f;
#pragma unroll
        for (int k = 0; k < 9; k++) s += nbr_mask[(node0 + nn) * 9 + k];
        h1sh[nn * 9 + i] = nbr_mask[(node0 + nn) * 9 + i] / s;
    }
    __syncthreads();
    {
        const float* C1f = (const float*)C1p;   // lo lane alias, stride 2
        for (int q = tid; q < NB * 9; q += 160) {
            int nn = q / 9, i = q % 9;
            float s = 0.f;
#pragma unroll
            for (int k = 0; k < 9; k++) s += C1f[(nn * 81 + i * 9 + k) * 2] * h1sh[nn * 9 + k];
            f1h1[nn * 9 + i] = s;
        }
    }
    __syncthreads();

    const int c2b = tpl * 32;

    // f2p[mp] = (sum_k C2[k,m]^2)/8 ; qp[mp] = 0.125*sum_k C2[k,m]
    u64 f2p[4], qp[4];
    {
        const u64 EIGHTH = pk1(0.125f);
#pragma unroll
        for (int mp = 0; mp < 4; mp++) {
            u64 c0 = C2p[c2b + mp];
            u64 sq = mul2(c0, c0);
            u64 sl = c0;
#pragma unroll
            for (int k = 1; k < 8; k++) {
                u64 c = C2p[c2b + k * 4 + mp];
                sq = fma2(c, c, sq);
                sl = add2(sl, c);
            }
            f2p[mp] = mul2(sq, EIGHTH);
            qp[mp]  = mul2(sl, EIGHTH);
        }
    }

    // S = -5*(R + f1h1[i] + f2h2[m]) packed into shared
    {
        const u64 NEG5 = pk1(-5.f);
#pragma unroll
        for (int i = 0; i < 9; i++) {
            int id = idxs[nl * 9 + i];
            const float4* rp = (const float4*)(g_R + (size_t)id * 80 + tpl * 8);
            float4 r0 = rp[0], r1 = rp[1];
            u64 fi2 = pk1(f1h1[nl * 9 + i]);
            u64 rr[4] = { pk2(r0.x, r0.y), pk2(r0.z, r0.w), pk2(r1.x, r1.y), pk2(r1.z, r1.w) };
#pragma unroll
            for (int mp = 0; mp < 4; mp++)
                Msh2[(i * 4 + mp) * 160 + tid] =
                    mul2(NEG5, add2(rr[mp], add2(fi2, f2p[mp])));
        }
    }

    float h1r[9];
#pragma unroll
    for (int i = 0; i < 9; i++) h1r[i] = h1sh[nl * 9 + i];

    const u64 TEN2 = pk1(10.f);
    const u64 M1   = pk1(-1.f);
    const u64 M01  = pk1(-0.1f);

    u64 Tp[36];    // coupling T (also reused as A2 within an outer)
    u64 Wk[36];    // E = C1 @ (T@C2)

#pragma unroll 1
    for (int outer = 0; outer < 3; outer++) {
        if (outer == 0) {
            // rank-1: E = f1h1 (x) q
#pragma unroll
            for (int i = 0; i < 9; i++) {
                u64 fi2 = pk1(f1h1[nl * 9 + i]);
#pragma unroll
                for (int mp = 0; mp < 4; mp++) Wk[i * 4 + mp] = mul2(fi2, qp[mp]);
            }
        } else {
            // Tp <- T@C2 in place (row-local)
#pragma unroll
            for (int i = 0; i < 9; i++) {
                float tv[8];
                upk(Tp[i * 4 + 0], tv[0], tv[1]); upk(Tp[i * 4 + 1], tv[2], tv[3]);
                upk(Tp[i * 4 + 2], tv[4], tv[5]); upk(Tp[i * 4 + 3], tv[6], tv[7]);
                u64 acc[4];
                u64 tk = pk1(tv[0]);
#pragma unroll
                for (int mp = 0; mp < 4; mp++) acc[mp] = mul2(tk, C2p[c2b + mp]);
#pragma unroll
                for (int k = 1; k < 8; k++) {
                    tk = pk1(tv[k]);
#pragma unroll
                    for (int mp = 0; mp < 4; mp++)
                        acc[mp] = fma2(tk, C2p[c2b + k * 4 + mp], acc[mp]);
                }
#pragma unroll
                for (int mp = 0; mp < 4; mp++) Tp[i * 4 + mp] = acc[mp];
            }
            // Wk = C1 @ Tp
#pragma unroll
            for (int i = 0; i < 9; i++) {
                const u64* c1 = C1p + nl * 81 + i * 9;
                u64 ck = c1[0];
                u64 e0 = mul2(ck, Tp[0]), e1 = mul2(ck, Tp[1]),
                    e2 = mul2(ck, Tp[2]), e3 = mul2(ck, Tp[3]);
#pragma unroll
                for (int k = 1; k < 9; k++) {
                    ck = c1[k];
                    e0 = fma2(ck, Tp[k * 4 + 0], e0);
                    e1 = fma2(ck, Tp[k * 4 + 1], e1);
                    e2 = fma2(ck, Tp[k * 4 + 2], e2);
                    e3 = fma2(ck, Tp[k * 4 + 3], e3);
                }
                Wk[i * 4 + 0] = e0; Wk[i * 4 + 1] = e1;
                Wk[i * 4 + 2] = e2; Wk[i * 4 + 3] = e3;
            }
        }
        // A2 = exp(S + 10*E)  (into Tp)
#pragma unroll
        for (int i = 0; i < 9; i++) {
#pragma unroll
            for (int mp = 0; mp < 4; mp++) {
                u64 arg = fma2(TEN2, Wk[i * 4 + mp], Msh2[(i * 4 + mp) * 160 + tid]);
                float lo, hi; upk(arg, lo, hi);
                Tp[i * 4 + mp] = pk2(__expf(lo), __expf(hi));
            }
        }
        // sinkhorn on A2 (=Tp)
        u64 vp[4], ui2[9];
#pragma unroll
        for (int mp = 0; mp < 4; mp++) vp[mp] = pk1(1.f);
#pragma unroll 1
        for (int it = 0; it < 5; it++) {
#pragma unroll
            for (int i = 0; i < 9; i++) {
                u64 sp = mul2(Tp[i * 4 + 0], vp[0]);
                sp = fma2(Tp[i * 4 + 1], vp[1], sp);
                sp = fma2(Tp[i * 4 + 2], vp[2], sp);
                sp = fma2(Tp[i * 4 + 3], vp[3], sp);
                float lo, hi; upk(sp, lo, hi);
                ui2[i] = pk1(__fdividef(h1r[i], lo + hi + 1e-16f));
            }
            u64 sc[4];
#pragma unroll
            for (int mp = 0; mp < 4; mp++) sc[mp] = mul2(ui2[0], Tp[mp]);
#pragma unroll
            for (int i = 1; i < 9; i++)
#pragma unroll
                for (int mp = 0; mp < 4; mp++)
                    sc[mp] = fma2(ui2[i], Tp[i * 4 + mp], sc[mp]);
#pragma unroll
            for (int mp = 0; mp < 4; mp++) {
                float lo, hi; upk(sc[mp], lo, hi);
                vp[mp] = pk2(__fdividef(0.125f, lo + 1e-16f),
                             __fdividef(0.125f, hi + 1e-16f));
            }
        }
        // T = u * A2 * v
#pragma unroll
        for (int i = 0; i < 9; i++)
#pragma unroll
            for (int mp = 0; mp < 4; mp++)
                Tp[i * 4 + mp] = mul2(mul2(ui2[i], Tp[i * 4 + mp]), vp[mp]);
    }

    // final: Wk = T@C2 ; obj = sum T * ( -0.1*S - C1@Wk )
#pragma unroll
    for (int i = 0; i < 9; i++) {
        float tv[8];
        upk(Tp[i * 4 + 0], tv[0], tv[1]); upk(Tp[i * 4 + 1], tv[2], tv[3]);
        upk(Tp[i * 4 + 2], tv[4], tv[5]); upk(Tp[i * 4 + 3], tv[6], tv[7]);
        u64 acc[4];
        u64 tk = pk1(tv[0]);
#pragma unroll
        for (int mp = 0; mp < 4; mp++) acc[mp] = mul2(tk, C2p[c2b + mp]);
#pragma unroll
        for (int k = 1; k < 8; k++) {
            tk = pk1(tv[k]);
#pragma unroll
            for (int mp = 0; mp < 4; mp++)
                acc[mp] = fma2(tk, C2p[c2b + k * 4 + mp], acc[mp]);
        }
#pragma unroll
        for (int mp = 0; mp < 4; mp++) Wk[i * 4 + mp] = acc[mp];
    }
    u64 objp = pk1(0.f);
#pragma unroll
    for (int i = 0; i < 9; i++) {
        const u64* c1 = C1p + nl * 81 + i * 9;
        u64 ck = c1[0];
        u64 e[4];
#pragma unroll
        for (int mp = 0; mp < 4; mp++) e[mp] = mul2(ck, Wk[mp]);
#pragma unroll
        for (int k = 1; k < 9; k++) {
            ck = c1[k];
#pragma unroll
            for (int mp = 0; mp < 4; mp++)
                e[mp] = fma2(ck, Wk[k * 4 + mp], e[mp]);
        }
#pragma unroll
        for (int mp = 0; mp < 4; mp++) {
            u64 t2 = fma2(e[mp], M1, mul2(Msh2[(i * 4 + mp) * 160 + tid], M01));
            objp = fma2(Tp[i * 4 + mp], t2, objp);
        }
    }
    {
        float lo, hi; upk(objp, lo, hi);
        ysh[nl * 10 + tpl] = lo + hi;
    }
    __syncthreads();

    // head: out = relu(concat(h, y) @ Wlin + blin)
    if (tid < NB * NCLS) {
        int nn = tid / NCLS, c = tid % NCLS;
        float acc = blin[c];
#pragma unroll 8
        for (int k = 0; k < HID; k++)
            acc += h[(size_t)(node0 + nn) * HID + k] * Wlin[k * NCLS + c];
#pragma unroll
        for (int t = 0; t < NTPL; t++)
            acc += ysh[nn * 10 + t] * Wlin[(HID + t) * NCLS + c];
        out[(node0 + nn) * NCLS + c] = fmaxf(acc, 0.f);
    }
}

// ---------------- launch ----------------
extern "C" void kernel_launch(void* const* d_in, const int* in_sizes, int n_in,
                              void* d_out, int out_size)
{
    const float* x     = (const float*)d_in[0];
    const int*   ei    = (const int*)  d_in[1];
    const int*   nbr   = (const int*)  d_in[2];
    const float* mask  = (const float*)d_in[3];
    const float* Cl    = (const float*)d_in[4];
    const float* W1    = (const float*)d_in[5];
    const float* b1    = (const float*)d_in[6];
    const float* W2    = (const float*)d_in[7];
    const float* b2    = (const float*)d_in[8];
    const float* tadj  = (const float*)d_in[9];
    const float* tfeat = (const float*)d_in[10];
    const float* Wlin  = (const float*)d_in[11];
    const float* blin  = (const float*)d_in[12];
    float* out = (float*)d_out;

    const int* src = ei;
    const int* dst = ei + EE;

    void *pA, *pB, *pC, *pCnt;
    cudaGetSymbolAddress(&pA, g_bufA);
    cudaGetSymbolAddress(&pB, g_bufB);
    cudaGetSymbolAddress(&pC, g_bufC);
    cudaGetSymbolAddress(&pCnt, g_cnt);
    float* bufA = (float*)pA;
    float* bufB = (float*)pB;
    float* bufC = (float*)pC;

    cudaFuncSetAttribute(k_dist, cudaFuncAttributeMaxDynamicSharedMemorySize, DIST_SMEM);
    cudaFuncSetAttribute(k_gemm, cudaFuncAttributeMaxDynamicSharedMemorySize, GEMM_SMEM);

    cudaMemsetAsync(pCnt, 0, NN * sizeof(int));
    k_fill<<<(EE + 255) / 256, 256>>>(src, dst);
    k_dinv<<<(NN + 255) / 256, 256>>>();

    k_gemm<<<(NN + 63) / 64, 128, GEMM_SMEM>>>(x, W1, bufA, NN, FIN, FIN);
    k_gather<true><<<NN / 4, 256>>>(bufA, b1, bufB);

    k_gemm<<<(NN + 63) / 64, 128, GEMM_SMEM>>>(bufB, W2, bufA, NN, HID, HID);
    k_gather<false><<<NN / 4, 256>>>(bufA, b2, bufC);

    k_pr<<<(NN + 63) / 64, 256>>>(bufC, tfeat);

    k_dist<<<NN / NB, 160, DIST_SMEM>>>(bufC, nbr, mask, Cl, tadj, Wlin, blin, out);
}